// round 6
// baseline (speedup 1.0000x reference)
#include <cuda_runtime.h>
#include <cuda_bf16.h>
#include <cstdint>

// Problem constants
#define Bk 32
#define Hk 384
#define Wk 384
#define NPIX (Bk * Hk * Wk)
#define NELEM ((size_t)NPIX * 8)
#define NUM_ITERS 5

// Tiling
#define CTA_W 64          // pixels in x per CTA (4 warps x 16)
#define RY 4              // output rows per step per warp
#define TY 96             // output rows per CTA
#define NROWS 14          // rolling window rows (2*RY + 6 -> single-barrier pipeline)
#define NPXB 72           // buffer pixels per row: 64 + 3 left + 5 right
#define ROWB (NPXB * 16)  // 1152 bytes per row
#define NTHREADS 128

// Device-global scratch (allocation-free)
__device__ __nv_bfloat16 g_Qb[2][NELEM];     // ping-pong q (bf16, [pix][8])
__device__ float g_U2[NELEM];                // b - u @ W (fp32)
__device__ float g_K2[49 * 64];              // folded conv kernel [tap][ci][cd]
__device__ uint32_t g_Bfrag[4 * 7 * 64];     // mma B frags [p][dy][lane][j] (uint2/lane)

// ---------------------------------------------------------------- PTX helpers
__device__ __forceinline__ uint32_t smem_u32(const void* p) {
    uint32_t a;
    asm("{ .reg .u64 t; cvta.to.shared.u64 t, %1; cvt.u32.u64 %0, t; }"
        : "=r"(a) : "l"(p));
    return a;
}

__device__ __forceinline__ void ldsm_x4(uint32_t& a0, uint32_t& a1,
                                        uint32_t& a2, uint32_t& a3, uint32_t addr) {
    asm volatile("ldmatrix.sync.aligned.m8n8.x4.shared.b16 {%0,%1,%2,%3}, [%4];"
                 : "=r"(a0), "=r"(a1), "=r"(a2), "=r"(a3) : "r"(addr));
}

__device__ __forceinline__ void mma_bf16(float& d0, float& d1, float& d2, float& d3,
                                         uint32_t a0, uint32_t a1, uint32_t a2, uint32_t a3,
                                         uint32_t b0, uint32_t b1) {
    asm volatile(
        "mma.sync.aligned.m16n8k16.row.col.f32.bf16.bf16.f32 "
        "{%0,%1,%2,%3}, {%4,%5,%6,%7}, {%8,%9}, {%0,%1,%2,%3};"
        : "+f"(d0), "+f"(d1), "+f"(d2), "+f"(d3)
        : "r"(a0), "r"(a1), "r"(a2), "r"(a3), "r"(b0), "r"(b1));
}

// cp.async with zero-fill via src-size operand (0 => no read, zero-fill 16B)
__device__ __forceinline__ void cp16z(uint32_t dst, const void* src, uint32_t sz) {
    asm volatile("cp.async.ca.shared.global [%0], [%1], 16, %2;"
                 :: "r"(dst), "l"(src), "r"(sz) : "memory");
}
#define CP_COMMIT() asm volatile("cp.async.commit_group;" ::: "memory")
#define CP_WAIT0()  asm volatile("cp.async.wait_group 0;" ::: "memory")

// ---------------------------------------------------------------- prep kernels
__global__ void prep_weights(const float* __restrict__ k_int,
                             const float* __restrict__ W) {
    int idx = blockIdx.x * blockDim.x + threadIdx.x;
    if (idx >= 49 * 64) return;
    int tap = idx >> 6, ci = (idx >> 3) & 7, cd = idx & 7;
    float s = 0.0f;
#pragma unroll
    for (int co = 0; co < 8; co++) {
        if (co == ci) continue;
        s += k_int[(tap * 8 + ci) * 8 + co] * W[co * 8 + cd];
    }
    g_K2[idx] = s;
}

// B-fragment pack for m16n8k16, paired layout: [(p*7+dy)*64 + lane*2 + j]
// reg j, lane l -> k0=(l&3)*2+8j (k%8 = ci, k/8 = sub-tap j), n=l>>2
__global__ void prep_Bfrag(void) {
    int idx = blockIdx.x * blockDim.x + threadIdx.x;
    if (idx >= 4 * 7 * 64) return;
    int j  = idx & 1;
    int l  = (idx >> 1) & 31;
    int dy = (idx >> 6) % 7;
    int p  = idx / (64 * 7);
    int n  = l >> 2;
    int dx = 2 * p + j;
    float v0 = 0.0f, v1 = 0.0f;
    if (dx < 7) {
        int ci = (l & 3) * 2;
        v0 = g_K2[(dy * 7 + dx) * 64 + ci * 8 + n];
        v1 = g_K2[(dy * 7 + dx) * 64 + (ci + 1) * 8 + n];
    }
    __nv_bfloat162 pk = __floats2bfloat162_rn(v0, v1);
    g_Bfrag[idx] = *(uint32_t*)&pk;
}

__global__ void prep_pixels(const float* __restrict__ x,
                            const float* __restrict__ W,
                            const float* __restrict__ bvec) {
    int p = blockIdx.x * blockDim.x + threadIdx.x;
    if (p >= NPIX) return;
    const float4* xp = (const float4*)(x + (size_t)p * 8);
    float4 a = xp[0], b4 = xp[1];
    float v[8] = {a.x, a.y, a.z, a.w, b4.x, b4.y, b4.z, b4.w};
    float m = v[0];
#pragma unroll
    for (int c = 1; c < 8; c++) m = fmaxf(m, v[c]);
    float e[8], s = 0.0f;
#pragma unroll
    for (int c = 0; c < 8; c++) { e[c] = __expf(v[c] - m); s += e[c]; }
    float inv = 1.0f / s;
    float q[8], u[8];
#pragma unroll
    for (int c = 0; c < 8; c++) {
        q[c] = e[c] * inv;
        u[c] = -__logf(fmaxf(q[c], 1e-6f));
    }
    uint32_t pk[4];
#pragma unroll
    for (int c = 0; c < 4; c++) {
        __nv_bfloat162 t = __floats2bfloat162_rn(q[2 * c], q[2 * c + 1]);
        pk[c] = *(uint32_t*)&t;
    }
    ((uint4*)g_Qb[0])[p] = make_uint4(pk[0], pk[1], pk[2], pk[3]);

    float u2[8];
#pragma unroll
    for (int cd = 0; cd < 8; cd++) {
        float t = bvec[cd];
#pragma unroll
        for (int c = 0; c < 8; c++) t -= u[c] * W[c * 8 + cd];
        u2[cd] = t;
    }
    float4* up = (float4*)(&g_U2[(size_t)p * 8]);
    up[0] = make_float4(u2[0], u2[1], u2[2], u2[3]);
    up[1] = make_float4(u2[4], u2[5], u2[6], u2[7]);
}

// ---------------------------------------------------------------- main kernel
__global__ void __launch_bounds__(NTHREADS, 7)
mrf_hmma(int src, int dst, float* __restrict__ dlogits, int last) {
    __shared__ __align__(128) __nv_bfloat16 sq[NROWS * NPXB * 8];  // 16128 B
    __shared__ __align__(128) uint32_t sBf[4 * 7 * 64];            // 7168 B

    const int tid  = threadIdx.x;
    const int warp = tid >> 5;
    const int lane = tid & 31;
    const int x0 = blockIdx.x * CTA_W;
    const int y0 = blockIdx.y * TY;
    const int img = blockIdx.z;

    const uint32_t sq_a = smem_u32(sq);

    // B fragments to smem
#pragma unroll
    for (int i = 0; i < 14; i++) sBf[tid + 128 * i] = g_Bfrag[tid + 128 * i];

    const uint4* __restrict__ qsrc = (const uint4*)g_Qb[src];
    const uint32_t imgoff = (uint32_t)img * (Hk * Wk);

    // Prologue: rows y0-3 .. y0+6 via cp.async
    for (int i = tid; i < 10 * NPXB; i += NTHREADS) {
        int row = i / NPXB, px = i % NPXB;
        int yin = y0 - 3 + row;
        int slot = (yin + NROWS) % NROWS;
        int gx = x0 - 3 + px;
        uint32_t ok = (gx >= 0 && gx < Wk && yin >= 0 && yin < Hk) ? 16u : 0u;
        int gxc = min(max(gx, 0), Wk - 1);
        int yc  = min(max(yin, 0), Hk - 1);
        cp16z(sq_a + (uint32_t)(slot * NPXB + px) * 16,
              qsrc + imgoff + (uint32_t)yc * Wk + gxc, ok);
    }
    CP_COMMIT();
    CP_WAIT0();
    __syncthreads();

    // Per-thread constants
    const int toff = (lane & 15) + (lane >> 4);
    const uint32_t abase = sq_a + (uint32_t)(16 * warp + toff) * 16;
    const int xq = x0 + 16 * warp + (lane >> 2);   // pixel P1; P2 = +8
    const int n0 = (lane & 3) * 2;
    const uint2* __restrict__ sBf2 = (const uint2*)sBf;

    const int steps = TY / RY;
#pragma unroll 1
    for (int s = 0; s < steps; s++) {
        const int y = y0 + RY * s;

        // Issue async copies for the NEXT step's 4 input rows right away:
        // slots (y+7..y+10) mod 14 are disjoint from this step's read window
        // (y-3..y+6) mod 14, and the previous barrier guarantees slot reuse
        // safety. Copies drain behind the whole MMA + epilogue.
        if (s + 1 < steps) {
#pragma unroll
            for (int rep = 0; rep < 3; rep++) {
                int idx = tid + NTHREADS * rep;
                if (idx < RY * NPXB) {
                    int row = idx / NPXB, px = idx % NPXB;
                    int yin = y + 7 + row;
                    int gx = x0 - 3 + px;
                    uint32_t ok = (gx >= 0 && gx < Wk && yin < Hk) ? 16u : 0u;
                    int gxc = min(max(gx, 0), Wk - 1);
                    int yc  = min(yin, Hk - 1);
                    int slot = yin % NROWS;
                    cp16z(sq_a + (uint32_t)(slot * NPXB + px) * 16,
                          qsrc + imgoff + (uint32_t)yc * Wk + gxc, ok);
                }
            }
        }
        CP_COMMIT();

        // U2 prefetch for the 4 output rows (overlaps MMA)
        const uint32_t up0 = imgoff + (uint32_t)y * Wk + xq;
        float2 u2a[4], u2b[4];
#pragma unroll
        for (int r = 0; r < 4; r++) {
            u2a[r] = *(const float2*)(g_U2 + ((size_t)(up0 + r * Wk)) * 8 + n0);
            u2b[r] = *(const float2*)(g_U2 + ((size_t)(up0 + r * Wk + 8)) * 8 + n0);
        }

        float acc[4][4];
#pragma unroll
        for (int r = 0; r < 4; r++)
#pragma unroll
            for (int c = 0; c < 4; c++) acc[r][c] = 0.0f;

#pragma unroll
        for (int p = 0; p < 4; p++) {
            uint2 b[7];
#pragma unroll
            for (int dy = 0; dy < 7; dy++)
                b[dy] = sBf2[(p * 7 + dy) * 32 + lane];
#pragma unroll
            for (int i = 0; i < 10; i++) {
                int slot = (y + 11 + i) % NROWS;   // (y - 3 + i) mod NROWS
                uint32_t a0, a1, a2, a3;
                ldsm_x4(a0, a1, a2, a3, abase + (uint32_t)slot * ROWB + p * 32);
#pragma unroll
                for (int r = 0; r < 4; r++) {
                    int dy = i - r;
                    if (dy >= 0 && dy <= 6)
                        mma_bf16(acc[r][0], acc[r][1], acc[r][2], acc[r][3],
                                 a0, a1, a2, a3, b[dy].x, b[dy].y);
                }
            }
        }

        // Epilogue: logits = U2 - penalty; softmax (or raw logits on last iter)
#pragma unroll
        for (int r = 0; r < 4; r++) {
            const uint32_t pix1 = up0 + (uint32_t)r * Wk;
            const uint32_t pix2 = pix1 + 8;
            float l0 = u2a[r].x - acc[r][0];
            float l1 = u2a[r].y - acc[r][1];
            float l2 = u2b[r].x - acc[r][2];
            float l3 = u2b[r].y - acc[r][3];

            if (last) {
                *(float2*)(dlogits + (size_t)pix1 * 8 + n0) = make_float2(l0, l1);
                *(float2*)(dlogits + (size_t)pix2 * 8 + n0) = make_float2(l2, l3);
            } else {
                float m1 = fmaxf(l0, l1);
                m1 = fmaxf(m1, __shfl_xor_sync(0xffffffffu, m1, 1));
                m1 = fmaxf(m1, __shfl_xor_sync(0xffffffffu, m1, 2));
                float e0 = __expf(l0 - m1), e1 = __expf(l1 - m1);
                float s1 = e0 + e1;
                s1 += __shfl_xor_sync(0xffffffffu, s1, 1);
                s1 += __shfl_xor_sync(0xffffffffu, s1, 2);
                float inv1 = 1.0f / s1;

                float m2 = fmaxf(l2, l3);
                m2 = fmaxf(m2, __shfl_xor_sync(0xffffffffu, m2, 1));
                m2 = fmaxf(m2, __shfl_xor_sync(0xffffffffu, m2, 2));
                float e2 = __expf(l2 - m2), e3 = __expf(l3 - m2);
                float s2 = e2 + e3;
                s2 += __shfl_xor_sync(0xffffffffu, s2, 1);
                s2 += __shfl_xor_sync(0xffffffffu, s2, 2);
                float inv2 = 1.0f / s2;

                __nv_bfloat162 q1 = __floats2bfloat162_rn(e0 * inv1, e1 * inv1);
                __nv_bfloat162 q2 = __floats2bfloat162_rn(e2 * inv2, e3 * inv2);
                uint32_t* qdst = (uint32_t*)g_Qb[dst];
                qdst[(size_t)pix1 * 4 + (lane & 3)] = *(uint32_t*)&q1;
                qdst[(size_t)pix2 * 4 + (lane & 3)] = *(uint32_t*)&q2;
            }
        }

        CP_WAIT0();
        __syncthreads();   // single barrier per step: copies visible, reads done
    }
}

// ---------------------------------------------------------------- launch
extern "C" void kernel_launch(void* const* d_in, const int* in_sizes, int n_in,
                              void* d_out, int out_size) {
    const float* x          = (const float*)d_in[0];
    const float* k_internal = (const float*)d_in[1];
    const float* k_scale_w  = (const float*)d_in[2];
    const float* k_scale_b  = (const float*)d_in[3];
    float* out = (float*)d_out;

    prep_weights<<<(49 * 64 + 255) / 256, 256>>>(k_internal, k_scale_w);
    prep_Bfrag<<<7, 256>>>();
    prep_pixels<<<NPIX / 256, 256>>>(x, k_scale_w, k_scale_b);

    dim3 grid(Wk / CTA_W, Hk / TY, Bk);   // (6, 4, 32) = 768 CTAs
    int src = 0;
    for (int it = 0; it < NUM_ITERS; ++it) {
        int last = (it == NUM_ITERS - 1) ? 1 : 0;
        mrf_hmma<<<grid, NTHREADS>>>(src, 1 - src, out, last);
        src = 1 - src;
    }
}

// round 7
// speedup vs baseline: 1.0941x; 1.0941x over previous
#include <cuda_runtime.h>
#include <cuda_bf16.h>
#include <cstdint>

// Problem constants
#define Bk 32
#define Hk 384
#define Wk 384
#define NPIX (Bk * Hk * Wk)
#define NELEM ((size_t)NPIX * 8)
#define NUM_ITERS 5

// Tiling: warp-private pipelines, no intra-loop barriers
#define CTA_W 64          // pixels in x per CTA (4 warps x 16)
#define RY 4              // output rows per step per warp
#define TY 48             // output rows per CTA
#define NROWS 14          // ring slots (y+7..y+10 disjoint from y-3..y+6 mod 14)
#define WPX 24            // per-warp buffer pixels per row (16 + 3 halo left + 5 pad)
#define WROWB (WPX * 16)  // 384 bytes per row
#define NTHREADS 128

// Device-global scratch (allocation-free)
__device__ __nv_bfloat16 g_Qb[2][NELEM];     // ping-pong q (bf16, [pix][8])
__device__ float g_U2[NELEM];                // b - u @ W (fp32)
__device__ float g_K2[49 * 64];              // folded conv kernel [tap][ci][cd]
__device__ uint32_t g_Bfrag[4 * 7 * 64];     // mma B frags [p][dy][lane][j]

// ---------------------------------------------------------------- PTX helpers
__device__ __forceinline__ uint32_t smem_u32(const void* p) {
    uint32_t a;
    asm("{ .reg .u64 t; cvta.to.shared.u64 t, %1; cvt.u32.u64 %0, t; }"
        : "=r"(a) : "l"(p));
    return a;
}

__device__ __forceinline__ void ldsm_x4(uint32_t& a0, uint32_t& a1,
                                        uint32_t& a2, uint32_t& a3, uint32_t addr) {
    asm volatile("ldmatrix.sync.aligned.m8n8.x4.shared.b16 {%0,%1,%2,%3}, [%4];"
                 : "=r"(a0), "=r"(a1), "=r"(a2), "=r"(a3) : "r"(addr));
}

__device__ __forceinline__ void mma_bf16(float& d0, float& d1, float& d2, float& d3,
                                         uint32_t a0, uint32_t a1, uint32_t a2, uint32_t a3,
                                         uint32_t b0, uint32_t b1) {
    asm volatile(
        "mma.sync.aligned.m16n8k16.row.col.f32.bf16.bf16.f32 "
        "{%0,%1,%2,%3}, {%4,%5,%6,%7}, {%8,%9}, {%0,%1,%2,%3};"
        : "+f"(d0), "+f"(d1), "+f"(d2), "+f"(d3)
        : "r"(a0), "r"(a1), "r"(a2), "r"(a3), "r"(b0), "r"(b1));
}

// cp.async with zero-fill via src-size operand (0 => no read, zero-fill 16B)
__device__ __forceinline__ void cp16z(uint32_t dst, const void* src, uint32_t sz) {
    asm volatile("cp.async.ca.shared.global [%0], [%1], 16, %2;"
                 :: "r"(dst), "l"(src), "r"(sz) : "memory");
}
#define CP_COMMIT() asm volatile("cp.async.commit_group;" ::: "memory")
#define CP_WAIT1()  asm volatile("cp.async.wait_group 1;" ::: "memory")

// ---------------------------------------------------------------- prep kernels
__global__ void prep_weights(const float* __restrict__ k_int,
                             const float* __restrict__ W) {
    int idx = blockIdx.x * blockDim.x + threadIdx.x;
    if (idx >= 49 * 64) return;
    int tap = idx >> 6, ci = (idx >> 3) & 7, cd = idx & 7;
    float s = 0.0f;
#pragma unroll
    for (int co = 0; co < 8; co++) {
        if (co == ci) continue;
        s += k_int[(tap * 8 + ci) * 8 + co] * W[co * 8 + cd];
    }
    g_K2[idx] = s;
}

// B-fragment pack (paired): [(p*7+dy)*64 + lane*2 + j]
__global__ void prep_Bfrag(void) {
    int idx = blockIdx.x * blockDim.x + threadIdx.x;
    if (idx >= 4 * 7 * 64) return;
    int j  = idx & 1;
    int l  = (idx >> 1) & 31;
    int dy = (idx >> 6) % 7;
    int p  = idx / (64 * 7);
    int n  = l >> 2;
    int dx = 2 * p + j;
    float v0 = 0.0f, v1 = 0.0f;
    if (dx < 7) {
        int ci = (l & 3) * 2;
        v0 = g_K2[(dy * 7 + dx) * 64 + ci * 8 + n];
        v1 = g_K2[(dy * 7 + dx) * 64 + (ci + 1) * 8 + n];
    }
    __nv_bfloat162 pk = __floats2bfloat162_rn(v0, v1);
    g_Bfrag[idx] = *(uint32_t*)&pk;
}

__global__ void prep_pixels(const float* __restrict__ x,
                            const float* __restrict__ W,
                            const float* __restrict__ bvec) {
    int p = blockIdx.x * blockDim.x + threadIdx.x;
    if (p >= NPIX) return;
    const float4* xp = (const float4*)(x + (size_t)p * 8);
    float4 a = xp[0], b4 = xp[1];
    float v[8] = {a.x, a.y, a.z, a.w, b4.x, b4.y, b4.z, b4.w};
    float m = v[0];
#pragma unroll
    for (int c = 1; c < 8; c++) m = fmaxf(m, v[c]);
    float e[8], s = 0.0f;
#pragma unroll
    for (int c = 0; c < 8; c++) { e[c] = __expf(v[c] - m); s += e[c]; }
    float inv = 1.0f / s;
    float q[8], u[8];
#pragma unroll
    for (int c = 0; c < 8; c++) {
        q[c] = e[c] * inv;
        u[c] = -__logf(fmaxf(q[c], 1e-6f));
    }
    uint32_t pk[4];
#pragma unroll
    for (int c = 0; c < 4; c++) {
        __nv_bfloat162 t = __floats2bfloat162_rn(q[2 * c], q[2 * c + 1]);
        pk[c] = *(uint32_t*)&t;
    }
    ((uint4*)g_Qb[0])[p] = make_uint4(pk[0], pk[1], pk[2], pk[3]);

    float u2[8];
#pragma unroll
    for (int cd = 0; cd < 8; cd++) {
        float t = bvec[cd];
#pragma unroll
        for (int c = 0; c < 8; c++) t -= u[c] * W[c * 8 + cd];
        u2[cd] = t;
    }
    float4* up = (float4*)(&g_U2[(size_t)p * 8]);
    up[0] = make_float4(u2[0], u2[1], u2[2], u2[3]);
    up[1] = make_float4(u2[4], u2[5], u2[6], u2[7]);
}

// ---------------------------------------------------------------- main kernel
// Warp-private ring buffers -> no __syncthreads in the main loop; each warp
// runs its own cp.async pipeline with one group in flight (wait_group 1).
__global__ void __launch_bounds__(NTHREADS, 7)
mrf_hmma(int src, int dst, float* __restrict__ dlogits, int last) {
    __shared__ __align__(128) __nv_bfloat16 sq[4 * NROWS * WPX * 8];  // 21504 B
    __shared__ __align__(128) uint32_t sBf[4 * 7 * 64];               // 7168 B

    const int tid  = threadIdx.x;
    const int warp = tid >> 5;
    const int lane = tid & 31;
    const int x0w = blockIdx.x * CTA_W + 16 * warp;  // this warp's x start
    const int y0 = blockIdx.y * TY;
    const int img = blockIdx.z;

    const uint32_t wbase = smem_u32(sq) + (uint32_t)warp * (NROWS * WROWB);

    // B fragments to smem (one barrier total)
#pragma unroll
    for (int i = 0; i < 14; i++) sBf[tid + 128 * i] = g_Bfrag[tid + 128 * i];

    const uint4* __restrict__ qsrc = (const uint4*)g_Qb[src];
    const uint32_t imgoff = (uint32_t)img * (Hk * Wk);

    // Prologue: rows y0-3 .. y0+6 (this warp's 24-px stripe), group G_pro
    for (int i = lane; i < 10 * WPX; i += 32) {
        int row = i / WPX, px = i % WPX;
        int yin = y0 - 3 + row;
        int slot = (yin + NROWS) % NROWS;
        int gx = x0w - 3 + px;
        uint32_t ok = (gx >= 0 && gx < Wk && yin >= 0 && yin < Hk) ? 16u : 0u;
        int gxc = min(max(gx, 0), Wk - 1);
        int yc  = min(max(yin, 0), Hk - 1);
        cp16z(wbase + (uint32_t)(slot * WPX + px) * 16,
              qsrc + imgoff + (uint32_t)yc * Wk + gxc, ok);
    }
    CP_COMMIT();
    __syncthreads();   // sBf visible to all warps (also covers nothing else)

    // Per-thread constants (ldmatrix m16k16 address map)
    const int toff = (lane & 15) + (lane >> 4);
    const uint32_t abase = wbase + (uint32_t)toff * 16;
    const int xq = x0w + (lane >> 2);              // output pixel P1; P2 = +8
    const int n0 = (lane & 3) * 2;
    const uint2* __restrict__ sBf2 = (const uint2*)sBf;

    const int steps = TY / RY;
#pragma unroll 1
    for (int s = 0; s < steps; s++) {
        const int y = y0 + RY * s;

        // Issue next step's rows (slots y+7..y+10 mod 14, disjoint from the
        // current read window y-3..y+6 mod 14). Group G_s.
        if (s + 1 < steps) {
#pragma unroll
            for (int rep = 0; rep < 3; rep++) {
                int idx = lane + 32 * rep;
                int row = idx / WPX, px = idx % WPX;
                int yin = y + 7 + row;
                int gx = x0w - 3 + px;
                uint32_t ok = (gx >= 0 && gx < Wk && yin < Hk) ? 16u : 0u;
                int gxc = min(max(gx, 0), Wk - 1);
                int yc  = min(yin, Hk - 1);
                int slot = yin % NROWS;
                cp16z(wbase + (uint32_t)(slot * WPX + px) * 16,
                      qsrc + imgoff + (uint32_t)yc * Wk + gxc, ok);
            }
        }
        CP_COMMIT();
        CP_WAIT1();   // wait for G_{s-1} (this step's rows); G_s stays in flight

        // U2 prefetch for the 4 output rows (overlaps MMA)
        const uint32_t up0 = imgoff + (uint32_t)y * Wk + xq;
        float2 u2a[4], u2b[4];
#pragma unroll
        for (int r = 0; r < 4; r++) {
            u2a[r] = *(const float2*)(g_U2 + ((size_t)(up0 + r * Wk)) * 8 + n0);
            u2b[r] = *(const float2*)(g_U2 + ((size_t)(up0 + r * Wk + 8)) * 8 + n0);
        }

        float acc[4][4];
#pragma unroll
        for (int r = 0; r < 4; r++)
#pragma unroll
            for (int c = 0; c < 4; c++) acc[r][c] = 0.0f;

#pragma unroll
        for (int p = 0; p < 4; p++) {
            uint2 b[7];
#pragma unroll
            for (int dy = 0; dy < 7; dy++)
                b[dy] = sBf2[(p * 7 + dy) * 32 + lane];
#pragma unroll
            for (int i = 0; i < 10; i++) {
                int slot = (y + 11 + i) % NROWS;   // (y - 3 + i) mod NROWS
                uint32_t a0, a1, a2, a3;
                ldsm_x4(a0, a1, a2, a3, abase + (uint32_t)slot * WROWB + p * 32);
#pragma unroll
                for (int r = 0; r < 4; r++) {
                    int dy = i - r;
                    if (dy >= 0 && dy <= 6)
                        mma_bf16(acc[r][0], acc[r][1], acc[r][2], acc[r][3],
                                 a0, a1, a2, a3, b[dy].x, b[dy].y);
                }
            }
        }

        // Epilogue: logits = U2 - penalty; softmax (or raw logits on last iter)
#pragma unroll
        for (int r = 0; r < 4; r++) {
            const uint32_t pix1 = up0 + (uint32_t)r * Wk;
            const uint32_t pix2 = pix1 + 8;
            float l0 = u2a[r].x - acc[r][0];
            float l1 = u2a[r].y - acc[r][1];
            float l2 = u2b[r].x - acc[r][2];
            float l3 = u2b[r].y - acc[r][3];

            if (last) {
                *(float2*)(dlogits + (size_t)pix1 * 8 + n0) = make_float2(l0, l1);
                *(float2*)(dlogits + (size_t)pix2 * 8 + n0) = make_float2(l2, l3);
            } else {
                float m1 = fmaxf(l0, l1);
                m1 = fmaxf(m1, __shfl_xor_sync(0xffffffffu, m1, 1));
                m1 = fmaxf(m1, __shfl_xor_sync(0xffffffffu, m1, 2));
                float e0 = __expf(l0 - m1), e1 = __expf(l1 - m1);
                float s1 = e0 + e1;
                s1 += __shfl_xor_sync(0xffffffffu, s1, 1);
                s1 += __shfl_xor_sync(0xffffffffu, s1, 2);
                float inv1 = 1.0f / s1;

                float m2 = fmaxf(l2, l3);
                m2 = fmaxf(m2, __shfl_xor_sync(0xffffffffu, m2, 1));
                m2 = fmaxf(m2, __shfl_xor_sync(0xffffffffu, m2, 2));
                float e2 = __expf(l2 - m2), e3 = __expf(l3 - m2);
                float s2 = e2 + e3;
                s2 += __shfl_xor_sync(0xffffffffu, s2, 1);
                s2 += __shfl_xor_sync(0xffffffffu, s2, 2);
                float inv2 = 1.0f / s2;

                __nv_bfloat162 q1 = __floats2bfloat162_rn(e0 * inv1, e1 * inv1);
                __nv_bfloat162 q2 = __floats2bfloat162_rn(e2 * inv2, e3 * inv2);
                uint32_t* qdst = (uint32_t*)g_Qb[dst];
                qdst[(size_t)pix1 * 4 + (lane & 3)] = *(uint32_t*)&q1;
                qdst[(size_t)pix2 * 4 + (lane & 3)] = *(uint32_t*)&q2;
            }
        }
        // no barrier: ring slots written by G_s are disjoint from every
        // window read before G_s's data is consumed (NROWS=14 proof above)
    }
}

// ---------------------------------------------------------------- launch
extern "C" void kernel_launch(void* const* d_in, const int* in_sizes, int n_in,
                              void* d_out, int out_size) {
    const float* x          = (const float*)d_in[0];
    const float* k_internal = (const float*)d_in[1];
    const float* k_scale_w  = (const float*)d_in[2];
    const float* k_scale_b  = (const float*)d_in[3];
    float* out = (float*)d_out;

    prep_weights<<<(49 * 64 + 255) / 256, 256>>>(k_internal, k_scale_w);
    prep_Bfrag<<<7, 256>>>();
    prep_pixels<<<NPIX / 256, 256>>>(x, k_scale_w, k_scale_b);

    dim3 grid(Wk / CTA_W, Hk / TY, Bk);   // (6, 8, 32) = 1536 CTAs
    int src = 0;
    for (int it = 0; it < NUM_ITERS; ++it) {
        int last = (it == NUM_ITERS - 1) ? 1 : 0;
        mrf_hmma<<<grid, NTHREADS>>>(src, 1 - src, out, last);
        src = 1 - src;
    }
}

// round 8
// speedup vs baseline: 1.1581x; 1.0585x over previous
#include <cuda_runtime.h>
#include <cuda_bf16.h>
#include <cstdint>

// Problem constants
#define Bk 32
#define Hk 384
#define Wk 384
#define NPIX (Bk * Hk * Wk)
#define NELEM ((size_t)NPIX * 8)
#define NUM_ITERS 5

// Tiling: warp-private pipelines, no intra-loop barriers
#define CTA_W 64          // pixels in x per CTA (4 warps x 16)
#define RY 4              // output rows per step per warp
#define TY 48             // output rows per CTA
#define NROWS 16          // ring slots (power of 2: slot math is one AND)
#define WPX 24            // per-warp buffer pixels per row (16 + 3 halo left + 5 pad)
#define WROWB (WPX * 16)  // 384 bytes per row
#define NTHREADS 128

// Device-global scratch (allocation-free)
__device__ __nv_bfloat16 g_Qb[2][NELEM];     // ping-pong q (bf16, [pix][8])
__device__ float g_U2[NELEM];                // b - u @ W (fp32)
__device__ float g_K2[49 * 64];              // folded conv kernel [tap][ci][cd]
__device__ uint32_t g_Bfrag[4 * 7 * 64];     // mma B frags [p][dy][lane][j]

// ---------------------------------------------------------------- PTX helpers
__device__ __forceinline__ uint32_t smem_u32(const void* p) {
    uint32_t a;
    asm("{ .reg .u64 t; cvta.to.shared.u64 t, %1; cvt.u32.u64 %0, t; }"
        : "=r"(a) : "l"(p));
    return a;
}

__device__ __forceinline__ void ldsm_x4(uint32_t& a0, uint32_t& a1,
                                        uint32_t& a2, uint32_t& a3, uint32_t addr) {
    asm volatile("ldmatrix.sync.aligned.m8n8.x4.shared.b16 {%0,%1,%2,%3}, [%4];"
                 : "=r"(a0), "=r"(a1), "=r"(a2), "=r"(a3) : "r"(addr));
}

__device__ __forceinline__ void mma_bf16(float& d0, float& d1, float& d2, float& d3,
                                         uint32_t a0, uint32_t a1, uint32_t a2, uint32_t a3,
                                         uint32_t b0, uint32_t b1) {
    asm volatile(
        "mma.sync.aligned.m16n8k16.row.col.f32.bf16.bf16.f32 "
        "{%0,%1,%2,%3}, {%4,%5,%6,%7}, {%8,%9}, {%0,%1,%2,%3};"
        : "+f"(d0), "+f"(d1), "+f"(d2), "+f"(d3)
        : "r"(a0), "r"(a1), "r"(a2), "r"(a3), "r"(b0), "r"(b1));
}

// cp.async with zero-fill via src-size operand (0 => no read, zero-fill 16B)
__device__ __forceinline__ void cp16z(uint32_t dst, const void* src, uint32_t sz) {
    asm volatile("cp.async.ca.shared.global [%0], [%1], 16, %2;"
                 :: "r"(dst), "l"(src), "r"(sz) : "memory");
}
#define CP_COMMIT() asm volatile("cp.async.commit_group;" ::: "memory")
#define CP_WAIT1()  asm volatile("cp.async.wait_group 1;" ::: "memory")

// ---------------------------------------------------------------- prep kernels
__global__ void prep_weights(const float* __restrict__ k_int,
                             const float* __restrict__ W) {
    int idx = blockIdx.x * blockDim.x + threadIdx.x;
    if (idx >= 49 * 64) return;
    int tap = idx >> 6, ci = (idx >> 3) & 7, cd = idx & 7;
    float s = 0.0f;
#pragma unroll
    for (int co = 0; co < 8; co++) {
        if (co == ci) continue;
        s += k_int[(tap * 8 + ci) * 8 + co] * W[co * 8 + cd];
    }
    g_K2[idx] = s;
}

// B-fragment pack (paired): [(p*7+dy)*64 + lane*2 + j]
__global__ void prep_Bfrag(void) {
    int idx = blockIdx.x * blockDim.x + threadIdx.x;
    if (idx >= 4 * 7 * 64) return;
    int j  = idx & 1;
    int l  = (idx >> 1) & 31;
    int dy = (idx >> 6) % 7;
    int p  = idx / (64 * 7);
    int n  = l >> 2;
    int dx = 2 * p + j;
    float v0 = 0.0f, v1 = 0.0f;
    if (dx < 7) {
        int ci = (l & 3) * 2;
        v0 = g_K2[(dy * 7 + dx) * 64 + ci * 8 + n];
        v1 = g_K2[(dy * 7 + dx) * 64 + (ci + 1) * 8 + n];
    }
    __nv_bfloat162 pk = __floats2bfloat162_rn(v0, v1);
    g_Bfrag[idx] = *(uint32_t*)&pk;
}

__global__ void prep_pixels(const float* __restrict__ x,
                            const float* __restrict__ W,
                            const float* __restrict__ bvec) {
    int p = blockIdx.x * blockDim.x + threadIdx.x;
    if (p >= NPIX) return;
    const float4* xp = (const float4*)(x + (size_t)p * 8);
    float4 a = xp[0], b4 = xp[1];
    float v[8] = {a.x, a.y, a.z, a.w, b4.x, b4.y, b4.z, b4.w};
    float m = v[0];
#pragma unroll
    for (int c = 1; c < 8; c++) m = fmaxf(m, v[c]);
    float e[8], s = 0.0f;
#pragma unroll
    for (int c = 0; c < 8; c++) { e[c] = __expf(v[c] - m); s += e[c]; }
    float inv = 1.0f / s;
    float q[8], u[8];
#pragma unroll
    for (int c = 0; c < 8; c++) {
        q[c] = e[c] * inv;
        u[c] = -__logf(fmaxf(q[c], 1e-6f));
    }
    uint32_t pk[4];
#pragma unroll
    for (int c = 0; c < 4; c++) {
        __nv_bfloat162 t = __floats2bfloat162_rn(q[2 * c], q[2 * c + 1]);
        pk[c] = *(uint32_t*)&t;
    }
    ((uint4*)g_Qb[0])[p] = make_uint4(pk[0], pk[1], pk[2], pk[3]);

    float u2[8];
#pragma unroll
    for (int cd = 0; cd < 8; cd++) {
        float t = bvec[cd];
#pragma unroll
        for (int c = 0; c < 8; c++) t -= u[c] * W[c * 8 + cd];
        u2[cd] = t;
    }
    float4* up = (float4*)(&g_U2[(size_t)p * 8]);
    up[0] = make_float4(u2[0], u2[1], u2[2], u2[3]);
    up[1] = make_float4(u2[4], u2[5], u2[6], u2[7]);
}

// ---------------------------------------------------------------- main kernel
// Warp-private ring buffers (16 slots, power-of-2 indexing), no __syncthreads
// in the main loop; per-warp cp.async pipeline with one group in flight.
__global__ void __launch_bounds__(NTHREADS, 7)
mrf_hmma(int src, int dst, float* __restrict__ dlogits, int last) {
    __shared__ __align__(128) __nv_bfloat16 sq[4 * NROWS * WPX * 8];  // 24576 B
    __shared__ __align__(128) uint32_t sBf[4 * 7 * 64];               // 7168 B

    const int tid  = threadIdx.x;
    const int warp = tid >> 5;
    const int lane = tid & 31;
    const int x0w = blockIdx.x * CTA_W + 16 * warp;  // this warp's x start
    const int y0 = blockIdx.y * TY;
    const int img = blockIdx.z;

    const uint32_t wbase = smem_u32(sq) + (uint32_t)warp * (NROWS * WROWB);

    // B fragments to smem (one barrier total)
#pragma unroll
    for (int i = 0; i < 14; i++) sBf[tid + 128 * i] = g_Bfrag[tid + 128 * i];

    const uint4* __restrict__ qsrc = (const uint4*)g_Qb[src];
    const uint32_t imgoff = (uint32_t)img * (Hk * Wk);

    // Prologue: rows y0-3 .. y0+6 (this warp's 24-px stripe)
    for (int i = lane; i < 10 * WPX; i += 32) {
        int row = i / WPX, px = i % WPX;
        int yin = y0 - 3 + row;
        int slot = (yin + NROWS) & (NROWS - 1);
        int gx = x0w - 3 + px;
        uint32_t ok = (gx >= 0 && gx < Wk && yin >= 0 && yin < Hk) ? 16u : 0u;
        int gxc = min(max(gx, 0), Wk - 1);
        int yc  = min(max(yin, 0), Hk - 1);
        cp16z(wbase + (uint32_t)(slot * WPX + px) * 16,
              qsrc + imgoff + (uint32_t)yc * Wk + gxc, ok);
    }
    CP_COMMIT();
    __syncthreads();   // sBf visible to all warps

    // Per-thread constants (ldmatrix m16k16 address map)
    const int toff = (lane & 15) + (lane >> 4);
    const uint32_t abase = wbase + (uint32_t)toff * 16;
    const int xq = x0w + (lane >> 2);              // output pixel P1; P2 = +8
    const int n0 = (lane & 3) * 2;
    const uint2* __restrict__ sBf2 = (const uint2*)sBf;

    const int steps = TY / RY;
#pragma unroll 1
    for (int s = 0; s < steps; s++) {
        const int y = y0 + RY * s;

        // Issue next step's rows: slots (y+7..y+10) & 15 are disjoint from the
        // current read window (y-3..y+6) & 15 (14 consecutive rows < 16).
        if (s + 1 < steps) {
#pragma unroll
            for (int rep = 0; rep < 3; rep++) {
                int idx = lane + 32 * rep;
                int row = idx / WPX, px = idx % WPX;
                int yin = y + 7 + row;
                int gx = x0w - 3 + px;
                uint32_t ok = (gx >= 0 && gx < Wk && yin < Hk) ? 16u : 0u;
                int gxc = min(max(gx, 0), Wk - 1);
                int yc  = min(yin, Hk - 1);
                int slot = yin & (NROWS - 1);
                cp16z(wbase + (uint32_t)(slot * WPX + px) * 16,
                      qsrc + imgoff + (uint32_t)yc * Wk + gxc, ok);
            }
        }
        CP_COMMIT();
        CP_WAIT1();   // this step's rows ready; next step's stay in flight

        // U2 prefetch for the 4 output rows (overlaps MMA)
        const uint32_t up0 = imgoff + (uint32_t)y * Wk + xq;
        float2 u2a[4], u2b[4];
#pragma unroll
        for (int r = 0; r < 4; r++) {
            u2a[r] = *(const float2*)(g_U2 + ((size_t)(up0 + r * Wk)) * 8 + n0);
            u2b[r] = *(const float2*)(g_U2 + ((size_t)(up0 + r * Wk + 8)) * 8 + n0);
        }

        float acc[4][4];
#pragma unroll
        for (int r = 0; r < 4; r++)
#pragma unroll
            for (int c = 0; c < 4; c++) acc[r][c] = 0.0f;

#pragma unroll
        for (int p = 0; p < 4; p++) {
            uint2 b[7];
#pragma unroll
            for (int dy = 0; dy < 7; dy++)
                b[dy] = sBf2[(p * 7 + dy) * 32 + lane];
#pragma unroll
            for (int i = 0; i < 10; i++) {
                int slot = (y + 13 + i) & (NROWS - 1);   // (y - 3 + i) & 15
                uint32_t a0, a1, a2, a3;
                ldsm_x4(a0, a1, a2, a3, abase + (uint32_t)slot * WROWB + p * 32);
#pragma unroll
                for (int r = 0; r < 4; r++) {
                    int dy = i - r;
                    if (dy >= 0 && dy <= 6)
                        mma_bf16(acc[r][0], acc[r][1], acc[r][2], acc[r][3],
                                 a0, a1, a2, a3, b[dy].x, b[dy].y);
                }
            }
        }

        // Epilogue: logits = U2 - penalty; softmax (or raw logits on last iter)
#pragma unroll
        for (int r = 0; r < 4; r++) {
            const uint32_t pix1 = up0 + (uint32_t)r * Wk;
            const uint32_t pix2 = pix1 + 8;
            float l0 = u2a[r].x - acc[r][0];
            float l1 = u2a[r].y - acc[r][1];
            float l2 = u2b[r].x - acc[r][2];
            float l3 = u2b[r].y - acc[r][3];

            if (last) {
                *(float2*)(dlogits + (size_t)pix1 * 8 + n0) = make_float2(l0, l1);
                *(float2*)(dlogits + (size_t)pix2 * 8 + n0) = make_float2(l2, l3);
            } else {
                float m1 = fmaxf(l0, l1);
                m1 = fmaxf(m1, __shfl_xor_sync(0xffffffffu, m1, 1));
                m1 = fmaxf(m1, __shfl_xor_sync(0xffffffffu, m1, 2));
                float e0 = __expf(l0 - m1), e1 = __expf(l1 - m1);
                float s1 = e0 + e1;
                s1 += __shfl_xor_sync(0xffffffffu, s1, 1);
                s1 += __shfl_xor_sync(0xffffffffu, s1, 2);
                float inv1 = 1.0f / s1;

                float m2 = fmaxf(l2, l3);
                m2 = fmaxf(m2, __shfl_xor_sync(0xffffffffu, m2, 1));
                m2 = fmaxf(m2, __shfl_xor_sync(0xffffffffu, m2, 2));
                float e2 = __expf(l2 - m2), e3 = __expf(l3 - m2);
                float s2 = e2 + e3;
                s2 += __shfl_xor_sync(0xffffffffu, s2, 1);
                s2 += __shfl_xor_sync(0xffffffffu, s2, 2);
                float inv2 = 1.0f / s2;

                __nv_bfloat162 q1 = __floats2bfloat162_rn(e0 * inv1, e1 * inv1);
                __nv_bfloat162 q2 = __floats2bfloat162_rn(e2 * inv2, e3 * inv2);
                uint32_t* qdst = (uint32_t*)g_Qb[dst];
                qdst[(size_t)pix1 * 4 + (lane & 3)] = *(uint32_t*)&q1;
                qdst[(size_t)pix2 * 4 + (lane & 3)] = *(uint32_t*)&q2;
            }
        }
        // no barrier: ring invariant above
    }
}

// ---------------------------------------------------------------- launch
extern "C" void kernel_launch(void* const* d_in, const int* in_sizes, int n_in,
                              void* d_out, int out_size) {
    const float* x          = (const float*)d_in[0];
    const float* k_internal = (const float*)d_in[1];
    const float* k_scale_w  = (const float*)d_in[2];
    const float* k_scale_b  = (const float*)d_in[3];
    float* out = (float*)d_out;

    prep_weights<<<(49 * 64 + 255) / 256, 256>>>(k_internal, k_scale_w);
    prep_Bfrag<<<7, 256>>>();
    prep_pixels<<<NPIX / 256, 256>>>(x, k_scale_w, k_scale_b);

    dim3 grid(Wk / CTA_W, Hk / TY, Bk);   // (6, 8, 32) = 1536 CTAs
    int src = 0;
    for (int it = 0; it < NUM_ITERS; ++it) {
        int last = (it == NUM_ITERS - 1) ? 1 : 0;
        mrf_hmma<<<grid, NTHREADS>>>(src, 1 - src, out, last);
        src = 1 - src;
    }
}